// round 1
// baseline (speedup 1.0000x reference)
#include <cuda_runtime.h>
#include <math.h>

// ---------------------------------------------------------------------------
// Problem constants (from reference): B=8192, T=15, D=H=512, MAXL=8, CENTER=7
// ---------------------------------------------------------------------------
#define B_MAX   8192
#define T_WIN   15
#define D_DIM   512
#define H_DIM   512
#define G3      1536          // 3*H
#define MAXL    8

// ---------------------------------------------------------------------------
// Scratch (__device__ globals: allocation-free, ~950 MB total)
// ---------------------------------------------------------------------------
__device__ float g_xp0[B_MAX * MAXL * G3];   // fwd input projections (B,8,1536)
__device__ float g_xp1[B_MAX * MAXL * G3];   // bwd
__device__ float g_gh0[B_MAX * G3];          // fwd h@Whh^T per step
__device__ float g_gh1[B_MAX * G3];          // bwd
__device__ float g_h0 [B_MAX * H_DIM];       // fwd hidden state
__device__ float g_h1 [B_MAX * H_DIM];       // bwd
__device__ float g_hid[B_MAX * H_DIM];       // MLP hidden

// ---------------------------------------------------------------------------
// Generic NT SGEMM:  C[M,N] = A[M,K] @ B[N,K]^T   (+bias, +relu optional)
// Block tile 128x128, K-tile 16, 256 threads, 8x8 per-thread microtile,
// double-buffered shared memory, one __syncthreads per K-tile.
// MODE selects how A rows are sourced.
// ---------------------------------------------------------------------------
enum { MODE_GATHER = 0, MODE_PLAIN = 1, MODE_CONCAT = 2 };
enum { EPI_NONE = 0, EPI_BIAS = 1, EPI_BIAS_RELU = 2 };

struct GemmP {
    const float* A0;    // dir-0 A base (PLAIN) / concat half 0 (CONCAT)
    const float* A1;    // dir-1 A base (PLAIN) / concat half 1 (CONCAT)
    const float* B0;    // dir-0 weight (N,K)
    const float* B1;    // dir-1 weight (N,K)
    float*       C0;    // dir-0 output (M,N)
    float*       C1;    // dir-1 output
    const float* win;   // padded_window (GATHER)
    const int*   wlen;  // window_len (GATHER)
    const float* bias;  // epilogue bias (N,)
    int M, N, K;
};

template<int MODE, int EPI>
__global__ __launch_bounds__(256, 2)
void gemm_nt(GemmP p)
{
    __shared__ float As[2][16][132];
    __shared__ float Bs[2][16][132];

    const int dir = blockIdx.z;
    const float* __restrict__ Bmat = dir ? p.B1 : p.B0;
    float* __restrict__ C          = dir ? p.C1 : p.C0;
    const int K = p.K;
    const int N = p.N;

    const int tid = threadIdx.x;
    const int bm  = blockIdx.y;
    const int bn  = blockIdx.x;

    // global-load mapping: 512 float4 slots per 128x16 tile, 2 per thread
    const int lr = tid >> 2;          // local row 0..63 (and +64)
    const int lc = (tid & 3) * 4;     // k offset within tile: 0,4,8,12

    // Resolve A row base pointers (fixed across the K loop except CONCAT)
    const float* arow0 = nullptr;
    const float* arow1 = nullptr;
    int arix = bm * 128 + lr;         // global A row of slot 0 (CONCAT path)

    if (MODE == MODE_GATHER) {
        #pragma unroll
        for (int q = 0; q < 2; ++q) {
            int r  = bm * 128 + lr + q * 64;
            int b  = r >> 3;
            int j  = r & 7;
            int wl = p.wlen[b];
            int idx;
            if (dir == 0) { int len = (wl - 1) / 2 + 1; idx = 8 - len + j; }
            else          { int len =  wl      / 2 + 1; idx = 6 + len - j; }
            idx = min(max(idx, 0), T_WIN - 1);
            const float* rp = p.win + ((size_t)b * T_WIN + idx) * D_DIM;
            if (q == 0) arow0 = rp; else arow1 = rp;
        }
    } else if (MODE == MODE_PLAIN) {
        const float* Abase = dir ? p.A1 : p.A0;
        arow0 = Abase + (size_t)(bm * 128 + lr) * K;
        arow1 = arow0 + (size_t)64 * K;
    }

    const float* brow0 = Bmat + (size_t)(bn * 128 + lr) * K;
    const float* brow1 = brow0 + (size_t)64 * K;

    const int tx = tid & 15;
    const int ty = tid >> 4;

    float acc[8][8];
    #pragma unroll
    for (int i = 0; i < 8; ++i)
        #pragma unroll
        for (int j = 0; j < 8; ++j) acc[i][j] = 0.f;

    float4 sa0, sa1, sb0, sb1;

#define LOAD_TILE(K0)                                                          \
    do {                                                                       \
        if (MODE == MODE_CONCAT) {                                             \
            const float* base = ((K0) < 512) ? p.A0 : p.A1;                    \
            int kk_ = ((K0) < 512) ? (K0) : (K0) - 512;                        \
            sa0 = *(const float4*)(base + (size_t)arix      * 512 + kk_ + lc); \
            sa1 = *(const float4*)(base + (size_t)(arix+64) * 512 + kk_ + lc); \
        } else {                                                               \
            sa0 = *(const float4*)(arow0 + (K0) + lc);                         \
            sa1 = *(const float4*)(arow1 + (K0) + lc);                         \
        }                                                                      \
        sb0 = *(const float4*)(brow0 + (K0) + lc);                             \
        sb1 = *(const float4*)(brow1 + (K0) + lc);                             \
    } while (0)

#define STORE_TILE(BUF)                                                        \
    do {                                                                       \
        _Pragma("unroll")                                                      \
        for (int i_ = 0; i_ < 4; ++i_) {                                       \
            As[BUF][lc + i_][lr]      = ((const float*)&sa0)[i_];              \
            As[BUF][lc + i_][lr + 64] = ((const float*)&sa1)[i_];              \
            Bs[BUF][lc + i_][lr]      = ((const float*)&sb0)[i_];              \
            Bs[BUF][lc + i_][lr + 64] = ((const float*)&sb1)[i_];              \
        }                                                                      \
    } while (0)

    LOAD_TILE(0);
    STORE_TILE(0);
    __syncthreads();

    const int KT = K / 16;
    int buf = 0;
    for (int kt = 0; kt < KT; ++kt) {
        const bool more = (kt + 1 < KT);
        if (more) LOAD_TILE((kt + 1) * 16);

        #pragma unroll
        for (int kk = 0; kk < 16; ++kk) {
            float a[8], b[8];
            *(float4*)&a[0] = *(const float4*)&As[buf][kk][ty * 8];
            *(float4*)&a[4] = *(const float4*)&As[buf][kk][ty * 8 + 4];
            *(float4*)&b[0] = *(const float4*)&Bs[buf][kk][tx * 8];
            *(float4*)&b[4] = *(const float4*)&Bs[buf][kk][tx * 8 + 4];
            #pragma unroll
            for (int i = 0; i < 8; ++i)
                #pragma unroll
                for (int j = 0; j < 8; ++j)
                    acc[i][j] += a[i] * b[j];
        }

        if (more) {
            STORE_TILE(buf ^ 1);
            __syncthreads();
            buf ^= 1;
        }
    }
#undef LOAD_TILE
#undef STORE_TILE

    // epilogue
    const int crow = bm * 128 + ty * 8;
    const int ccol = bn * 128 + tx * 8;
    float bv[8];
    if (EPI != EPI_NONE) {
        #pragma unroll
        for (int j = 0; j < 8; ++j) bv[j] = p.bias[ccol + j];
    }
    #pragma unroll
    for (int i = 0; i < 8; ++i) {
        float out[8];
        #pragma unroll
        for (int j = 0; j < 8; ++j) {
            float v = acc[i][j];
            if (EPI != EPI_NONE)      v += bv[j];
            if (EPI == EPI_BIAS_RELU) v  = fmaxf(v, 0.f);
            out[j] = v;
        }
        float* cp = C + (size_t)(crow + i) * N + ccol;
        *(float4*)(cp)     = *(float4*)&out[0];
        *(float4*)(cp + 4) = *(float4*)&out[4];
    }
}

// ---------------------------------------------------------------------------
// GRU gate update (one timestep, both directions via grid.z).
// r = sig(xr + bih_r + hr + bhh_r); z likewise;
// n = tanh(xn + bih_n + r*(hn + bhh_n)); h = (1-z)*n + z*h   (only if t < len)
// At t==0 both gh and h are implicitly zero (skips one GEMM per dir).
// ---------------------------------------------------------------------------
struct GateP {
    const float* xp0; const float* xp1;
    const float* gh0; const float* gh1;
    float*       h0;  float*       h1;
    const float* bih0; const float* bih1;
    const float* bhh0; const float* bhh1;
    const int*   wlen;
    int t;
};

__global__ void gru_gate(GateP p)
{
    const int dir = blockIdx.z;
    const int gi  = blockIdx.x * blockDim.x + threadIdx.x;  // float4 index
    const int b   = gi >> 7;           // 128 float4 per row (H=512)
    const int j   = (gi & 127) * 4;

    const int wl  = p.wlen[b];
    const int len = dir ? (wl / 2 + 1) : ((wl - 1) / 2 + 1);
    const int t   = p.t;
    if (t >= len) return;              // frozen past sequence end

    const float* xp = (dir ? p.xp1 : p.xp0) + ((size_t)(b * MAXL + t)) * G3 + j;
    float4 xr = *(const float4*)(xp);
    float4 xz = *(const float4*)(xp + 512);
    float4 xn = *(const float4*)(xp + 1024);

    const float* bih = (dir ? p.bih1 : p.bih0) + j;
    const float* bhh = (dir ? p.bhh1 : p.bhh0) + j;
    float4 br = *(const float4*)(bih);
    float4 bz = *(const float4*)(bih + 512);
    float4 bq = *(const float4*)(bih + 1024);
    float4 cr = *(const float4*)(bhh);
    float4 cz = *(const float4*)(bhh + 512);
    float4 cq = *(const float4*)(bhh + 1024);

    float* hp = (dir ? p.h1 : p.h0) + (size_t)b * H_DIM + j;
    float4 hr, hz, hq, hv;
    if (t > 0) {
        const float* gh = (dir ? p.gh1 : p.gh0) + (size_t)b * G3 + j;
        hr = *(const float4*)(gh);
        hz = *(const float4*)(gh + 512);
        hq = *(const float4*)(gh + 1024);
        hv = *(const float4*)(hp);
    } else {
        hr = hz = hq = make_float4(0.f, 0.f, 0.f, 0.f);
        hv = make_float4(0.f, 0.f, 0.f, 0.f);
    }

    float4 res;
#define GATE(c)                                                                \
    {                                                                          \
        float r = 1.f / (1.f + expf(-(xr.c + br.c + hr.c + cr.c)));            \
        float z = 1.f / (1.f + expf(-(xz.c + bz.c + hz.c + cz.c)));            \
        float n = tanhf(xn.c + bq.c + r * (hq.c + cq.c));                      \
        res.c = (1.f - z) * n + z * hv.c;                                      \
    }
    GATE(x) GATE(y) GATE(z) GATE(w)
#undef GATE
    *(float4*)hp = res;
}

// ---------------------------------------------------------------------------
// Launch sequence (graph-capturable: kernel launches only)
// ---------------------------------------------------------------------------
extern "C" void kernel_launch(void* const* d_in, const int* in_sizes, int n_in,
                              void* d_out, int out_size)
{
    const float* win   = (const float*)d_in[0];
    const int*   wlen  = (const int*)  d_in[1];
    const float* Wih_f = (const float*)d_in[2];
    const float* Whh_f = (const float*)d_in[3];
    const float* bih_f = (const float*)d_in[4];
    const float* bhh_f = (const float*)d_in[5];
    const float* Wih_b = (const float*)d_in[6];
    const float* Whh_b = (const float*)d_in[7];
    const float* bih_b = (const float*)d_in[8];
    const float* bhh_b = (const float*)d_in[9];
    const float* W1    = (const float*)d_in[10];
    const float* b1    = (const float*)d_in[11];
    const float* W2    = (const float*)d_in[12];
    const float* b2    = (const float*)d_in[13];
    float* out = (float*)d_out;

    const int Bn = in_sizes[1];  // batch (window_len element count)

    float *xp0, *xp1, *gh0, *gh1, *h0, *h1, *hid;
    cudaGetSymbolAddress((void**)&xp0, g_xp0);
    cudaGetSymbolAddress((void**)&xp1, g_xp1);
    cudaGetSymbolAddress((void**)&gh0, g_gh0);
    cudaGetSymbolAddress((void**)&gh1, g_gh1);
    cudaGetSymbolAddress((void**)&h0,  g_h0);
    cudaGetSymbolAddress((void**)&h1,  g_h1);
    cudaGetSymbolAddress((void**)&hid, g_hid);

    // --- 1) Input projections for all 8 steps, both directions (gathered) ---
    GemmP p1 = {};
    p1.win = win; p1.wlen = wlen;
    p1.B0 = Wih_f; p1.B1 = Wih_b;
    p1.C0 = xp0;   p1.C1 = xp1;
    p1.M = Bn * MAXL; p1.N = G3; p1.K = D_DIM;
    gemm_nt<MODE_GATHER, EPI_NONE>
        <<<dim3(G3 / 128, p1.M / 128, 2), 256>>>(p1);

    // --- 2) Recurrence: t=0 has h=0 (no GEMM needed); t=1..7 GEMM+gates ---
    GateP gp;
    gp.xp0 = xp0; gp.xp1 = xp1;
    gp.gh0 = gh0; gp.gh1 = gh1;
    gp.h0  = h0;  gp.h1  = h1;
    gp.bih0 = bih_f; gp.bih1 = bih_b;
    gp.bhh0 = bhh_f; gp.bhh1 = bhh_b;
    gp.wlen = wlen;

    const dim3 ggrid((Bn * (H_DIM / 4)) / 256, 1, 2);
    gp.t = 0;
    gru_gate<<<ggrid, 256>>>(gp);

    GemmP p2 = {};
    p2.A0 = h0; p2.A1 = h1;
    p2.B0 = Whh_f; p2.B1 = Whh_b;
    p2.C0 = gh0;   p2.C1 = gh1;
    p2.M = Bn; p2.N = G3; p2.K = H_DIM;
    for (int t = 1; t < MAXL; ++t) {
        gemm_nt<MODE_PLAIN, EPI_NONE>
            <<<dim3(G3 / 128, Bn / 128, 2), 256>>>(p2);
        gp.t = t;
        gru_gate<<<ggrid, 256>>>(gp);
    }

    // --- 3) MLP: relu([h_f,h_b] @ W1^T + b1) @ W2^T + b2 ---
    GemmP p3 = {};
    p3.A0 = h0; p3.A1 = h1;          // K-concat halves
    p3.B0 = W1; p3.B1 = W1;
    p3.C0 = hid; p3.C1 = hid;
    p3.bias = b1;
    p3.M = Bn; p3.N = H_DIM; p3.K = 2 * H_DIM;
    gemm_nt<MODE_CONCAT, EPI_BIAS_RELU>
        <<<dim3(H_DIM / 128, Bn / 128, 1), 256>>>(p3);

    GemmP p4 = {};
    p4.A0 = hid; p4.A1 = hid;
    p4.B0 = W2;  p4.B1 = W2;
    p4.C0 = out; p4.C1 = out;
    p4.bias = b2;
    p4.M = Bn; p4.N = H_DIM; p4.K = H_DIM;
    gemm_nt<MODE_PLAIN, EPI_BIAS>
        <<<dim3(H_DIM / 128, Bn / 128, 1), 256>>>(p4);
}

// round 2
// speedup vs baseline: 2.2677x; 2.2677x over previous
#include <cuda_runtime.h>
#include <math.h>

// ---------------------------------------------------------------------------
// Problem constants: B=8192, T=15, D=H=512, MAXL=8, CENTER=7
// ---------------------------------------------------------------------------
#define B_MAX   8192
#define T_WIN   15
#define D_DIM   512
#define H_DIM   512
#define G3      1536          // 3*H
#define MAXL    8
#define SPAD    20            // smem row pitch (floats): m*20 mod 32 conflict-free

// ---------------------------------------------------------------------------
// Scratch (__device__ globals)
// ---------------------------------------------------------------------------
__device__ float g_xp0[B_MAX * MAXL * G3];
__device__ float g_xp1[B_MAX * MAXL * G3];
__device__ float g_gh0[B_MAX * G3];
__device__ float g_gh1[B_MAX * G3];
__device__ float g_h0 [B_MAX * H_DIM];
__device__ float g_h1 [B_MAX * H_DIM];
__device__ float g_hid[B_MAX * H_DIM];

// ---------------------------------------------------------------------------
// PTX helpers
// ---------------------------------------------------------------------------
__device__ __forceinline__ unsigned f2tf32(float f) {
    unsigned r;
    asm("cvt.rna.tf32.f32 %0, %1;" : "=r"(r) : "f"(f));
    return r;
}

__device__ __forceinline__ void ldsm4(unsigned* r, const float* p) {
    unsigned addr = (unsigned)__cvta_generic_to_shared(p);
    asm volatile("ldmatrix.sync.aligned.m8n8.x4.shared.b16 {%0,%1,%2,%3}, [%4];"
                 : "=r"(r[0]), "=r"(r[1]), "=r"(r[2]), "=r"(r[3]) : "r"(addr));
}

__device__ __forceinline__ void mma_tf32(float* c, const unsigned* a,
                                         unsigned b0, unsigned b1) {
    asm volatile(
        "mma.sync.aligned.m16n8k8.row.col.f32.tf32.tf32.f32 "
        "{%0,%1,%2,%3}, {%4,%5,%6,%7}, {%8,%9}, {%0,%1,%2,%3};"
        : "+f"(c[0]), "+f"(c[1]), "+f"(c[2]), "+f"(c[3])
        : "r"(a[0]), "r"(a[1]), "r"(a[2]), "r"(a[3]), "r"(b0), "r"(b1));
}

// ---------------------------------------------------------------------------
// Tensor-core NT GEMM:  C[M,N] = A[M,K] @ B[N,K]^T  (+bias, +relu optional)
// Block 128x128, K-tile 16, 256 threads (8 warps of 32x64), double-buffered.
// A layout in smem: [m][k] (pitch 20); B layout: [n][k] (pitch 20).
// ---------------------------------------------------------------------------
enum { MODE_GATHER = 0, MODE_PLAIN = 1, MODE_CONCAT = 2 };
enum { EPI_NONE = 0, EPI_BIAS = 1, EPI_BIAS_RELU = 2 };

struct GemmP {
    const float* A0;
    const float* A1;
    const float* B0;
    const float* B1;
    float*       C0;
    float*       C1;
    const float* win;
    const int*   wlen;
    const float* bias;
    int M, N, K;
};

template<int MODE, int EPI>
__global__ __launch_bounds__(256, 1)
void gemm_tc(GemmP p)
{
    __shared__ float As[2][128][SPAD];
    __shared__ float Bs[2][128][SPAD];

    const int dir = blockIdx.z;
    const float* __restrict__ Bmat = dir ? p.B1 : p.B0;
    float* __restrict__ C          = dir ? p.C1 : p.C0;
    const int K = p.K;
    const int N = p.N;

    const int tid  = threadIdx.x;
    const int bm   = blockIdx.y;
    const int bn   = blockIdx.x;
    const int warp = tid >> 5;
    const int lane = tid & 31;
    const int wm   = (warp >> 1) * 32;     // warp M offset within block tile
    const int wn   = (warp & 1) * 64;      // warp N offset

    // ---- global-load mapping: 2 float4 rows each for A and B per thread ----
    const int lr = tid >> 2;               // 0..63 (and +64)
    const int lc = (tid & 3) * 4;          // k: 0,4,8,12

    const float* arow0 = nullptr;
    const float* arow1 = nullptr;
    int arix = bm * 128 + lr;              // CONCAT row index

    if (MODE == MODE_GATHER) {
        #pragma unroll
        for (int q = 0; q < 2; ++q) {
            int r  = bm * 128 + lr + q * 64;
            int b  = r >> 3;
            int j  = r & 7;
            int wl = p.wlen[b];
            int idx;
            if (dir == 0) { int len = (wl - 1) / 2 + 1; idx = 8 - len + j; }
            else          { int len =  wl      / 2 + 1; idx = 6 + len - j; }
            idx = min(max(idx, 0), T_WIN - 1);
            const float* rp = p.win + ((size_t)b * T_WIN + idx) * D_DIM;
            if (q == 0) arow0 = rp; else arow1 = rp;
        }
    } else if (MODE == MODE_PLAIN) {
        const float* Abase = dir ? p.A1 : p.A0;
        arow0 = Abase + (size_t)(bm * 128 + lr) * K;
        arow1 = arow0 + (size_t)64 * K;
    }

    const float* brow0 = Bmat + (size_t)(bn * 128 + lr) * K;
    const float* brow1 = brow0 + (size_t)64 * K;

    float acc[2][8][4];
    #pragma unroll
    for (int i = 0; i < 2; ++i)
        #pragma unroll
        for (int t = 0; t < 8; ++t)
            #pragma unroll
            for (int v = 0; v < 4; ++v) acc[i][t][v] = 0.f;

    float4 sa0, sa1, sb0, sb1;

#define LOAD_TILE(K0)                                                          \
    do {                                                                       \
        if (MODE == MODE_CONCAT) {                                             \
            const float* base = ((K0) < 512) ? p.A0 : p.A1;                    \
            int kk_ = ((K0) < 512) ? (K0) : (K0) - 512;                        \
            sa0 = *(const float4*)(base + (size_t)arix      * 512 + kk_ + lc); \
            sa1 = *(const float4*)(base + (size_t)(arix+64) * 512 + kk_ + lc); \
        } else {                                                               \
            sa0 = *(const float4*)(arow0 + (K0) + lc);                         \
            sa1 = *(const float4*)(arow1 + (K0) + lc);                         \
        }                                                                      \
        sb0 = *(const float4*)(brow0 + (K0) + lc);                             \
        sb1 = *(const float4*)(brow1 + (K0) + lc);                             \
    } while (0)

#define TF4(dst, src)                                                          \
    do {                                                                       \
        (dst).x = __uint_as_float(f2tf32((src).x));                            \
        (dst).y = __uint_as_float(f2tf32((src).y));                            \
        (dst).z = __uint_as_float(f2tf32((src).z));                            \
        (dst).w = __uint_as_float(f2tf32((src).w));                            \
    } while (0)

#define STORE_TILE(BUF)                                                        \
    do {                                                                       \
        float4 ca0, ca1, cb0, cb1;                                             \
        TF4(ca0, sa0); TF4(ca1, sa1); TF4(cb0, sb0); TF4(cb1, sb1);            \
        *(float4*)&As[BUF][lr     ][lc] = ca0;                                 \
        *(float4*)&As[BUF][lr + 64][lc] = ca1;                                 \
        *(float4*)&Bs[BUF][lr     ][lc] = cb0;                                 \
        *(float4*)&Bs[BUF][lr + 64][lc] = cb1;                                 \
    } while (0)

    LOAD_TILE(0);
    STORE_TILE(0);
    __syncthreads();

    const int KT = K / 16;
    int buf = 0;
    for (int kt = 0; kt < KT; ++kt) {
        const bool more = (kt + 1 < KT);
        if (more) LOAD_TILE((kt + 1) * 16);

        #pragma unroll
        for (int ks = 0; ks < 2; ++ks) {
            const int k0 = ks * 8;
            // A fragments: 2 x (m16 x k8) via one ldmatrix.x4 each
            unsigned a[2][4];
            #pragma unroll
            for (int i = 0; i < 2; ++i) {
                const float* ap =
                    &As[buf][wm + i * 16 + (lane & 15)][k0 + (lane >> 4) * 4];
                ldsm4(a[i], ap);
            }
            // B fragments: 8 x (n8 x k8) via 4 ldmatrix.x4 (2 n-tiles each)
            unsigned b[4][4];
            #pragma unroll
            for (int t4 = 0; t4 < 4; ++t4) {
                const float* bp =
                    &Bs[buf][wn + t4 * 16 + ((lane >> 4) << 3) + (lane & 7)]
                       [k0 + ((lane >> 3) & 1) * 4];
                ldsm4(b[t4], bp);
            }
            #pragma unroll
            for (int i = 0; i < 2; ++i)
                #pragma unroll
                for (int t4 = 0; t4 < 4; ++t4) {
                    mma_tf32(acc[i][2 * t4],     a[i], b[t4][0], b[t4][1]);
                    mma_tf32(acc[i][2 * t4 + 1], a[i], b[t4][2], b[t4][3]);
                }
        }

        if (more) {
            STORE_TILE(buf ^ 1);
            __syncthreads();
            buf ^= 1;
        }
    }
#undef LOAD_TILE
#undef STORE_TILE
#undef TF4

    // ---- epilogue: fragment (row = lane>>2 [+8], cols = 2*(lane&3)+{0,1}) ----
    const int qr = lane >> 2;
    const int qc = (lane & 3) * 2;
    #pragma unroll
    for (int i = 0; i < 2; ++i) {
        const int r0 = bm * 128 + wm + i * 16 + qr;
        #pragma unroll
        for (int t = 0; t < 8; ++t) {
            const int cc = bn * 128 + wn + t * 8 + qc;
            float v0 = acc[i][t][0], v1 = acc[i][t][1];
            float v2 = acc[i][t][2], v3 = acc[i][t][3];
            if (EPI != EPI_NONE) {
                float b0 = p.bias[cc], b1 = p.bias[cc + 1];
                v0 += b0; v1 += b1; v2 += b0; v3 += b1;
                if (EPI == EPI_BIAS_RELU) {
                    v0 = fmaxf(v0, 0.f); v1 = fmaxf(v1, 0.f);
                    v2 = fmaxf(v2, 0.f); v3 = fmaxf(v3, 0.f);
                }
            }
            *(float2*)(C + (size_t)r0      * N + cc) = make_float2(v0, v1);
            *(float2*)(C + (size_t)(r0 + 8) * N + cc) = make_float2(v2, v3);
        }
    }
}

// ---------------------------------------------------------------------------
// GRU gate update (unchanged from round 1 — already at HBM roof)
// ---------------------------------------------------------------------------
struct GateP {
    const float* xp0; const float* xp1;
    const float* gh0; const float* gh1;
    float*       h0;  float*       h1;
    const float* bih0; const float* bih1;
    const float* bhh0; const float* bhh1;
    const int*   wlen;
    int t;
};

__global__ void gru_gate(GateP p)
{
    const int dir = blockIdx.z;
    const int gi  = blockIdx.x * blockDim.x + threadIdx.x;
    const int b   = gi >> 7;
    const int j   = (gi & 127) * 4;

    const int wl  = p.wlen[b];
    const int len = dir ? (wl / 2 + 1) : ((wl - 1) / 2 + 1);
    const int t   = p.t;
    if (t >= len) return;

    const float* xp = (dir ? p.xp1 : p.xp0) + ((size_t)(b * MAXL + t)) * G3 + j;
    float4 xr = *(const float4*)(xp);
    float4 xz = *(const float4*)(xp + 512);
    float4 xn = *(const float4*)(xp + 1024);

    const float* bih = (dir ? p.bih1 : p.bih0) + j;
    const float* bhh = (dir ? p.bhh1 : p.bhh0) + j;
    float4 br = *(const float4*)(bih);
    float4 bz = *(const float4*)(bih + 512);
    float4 bq = *(const float4*)(bih + 1024);
    float4 cr = *(const float4*)(bhh);
    float4 cz = *(const float4*)(bhh + 512);
    float4 cq = *(const float4*)(bhh + 1024);

    float* hp = (dir ? p.h1 : p.h0) + (size_t)b * H_DIM + j;
    float4 hr, hz, hq, hv;
    if (t > 0) {
        const float* gh = (dir ? p.gh1 : p.gh0) + (size_t)b * G3 + j;
        hr = *(const float4*)(gh);
        hz = *(const float4*)(gh + 512);
        hq = *(const float4*)(gh + 1024);
        hv = *(const float4*)(hp);
    } else {
        hr = hz = hq = make_float4(0.f, 0.f, 0.f, 0.f);
        hv = make_float4(0.f, 0.f, 0.f, 0.f);
    }

    float4 res;
#define GATE(c)                                                                \
    {                                                                          \
        float r = 1.f / (1.f + expf(-(xr.c + br.c + hr.c + cr.c)));            \
        float z = 1.f / (1.f + expf(-(xz.c + bz.c + hz.c + cz.c)));            \
        float n = tanhf(xn.c + bq.c + r * (hq.c + cq.c));                      \
        res.c = (1.f - z) * n + z * hv.c;                                      \
    }
    GATE(x) GATE(y) GATE(z) GATE(w)
#undef GATE
    *(float4*)hp = res;
}

// ---------------------------------------------------------------------------
// Launch sequence (graph-capturable: kernel launches only)
// ---------------------------------------------------------------------------
extern "C" void kernel_launch(void* const* d_in, const int* in_sizes, int n_in,
                              void* d_out, int out_size)
{
    const float* win   = (const float*)d_in[0];
    const int*   wlen  = (const int*)  d_in[1];
    const float* Wih_f = (const float*)d_in[2];
    const float* Whh_f = (const float*)d_in[3];
    const float* bih_f = (const float*)d_in[4];
    const float* bhh_f = (const float*)d_in[5];
    const float* Wih_b = (const float*)d_in[6];
    const float* Whh_b = (const float*)d_in[7];
    const float* bih_b = (const float*)d_in[8];
    const float* bhh_b = (const float*)d_in[9];
    const float* W1    = (const float*)d_in[10];
    const float* b1    = (const float*)d_in[11];
    const float* W2    = (const float*)d_in[12];
    const float* b2    = (const float*)d_in[13];
    float* out = (float*)d_out;

    const int Bn = in_sizes[1];

    float *xp0, *xp1, *gh0, *gh1, *h0, *h1, *hid;
    cudaGetSymbolAddress((void**)&xp0, g_xp0);
    cudaGetSymbolAddress((void**)&xp1, g_xp1);
    cudaGetSymbolAddress((void**)&gh0, g_gh0);
    cudaGetSymbolAddress((void**)&gh1, g_gh1);
    cudaGetSymbolAddress((void**)&h0,  g_h0);
    cudaGetSymbolAddress((void**)&h1,  g_h1);
    cudaGetSymbolAddress((void**)&hid, g_hid);

    // --- 1) Input projections for all 8 steps, both directions (gathered) ---
    GemmP p1 = {};
    p1.win = win; p1.wlen = wlen;
    p1.B0 = Wih_f; p1.B1 = Wih_b;
    p1.C0 = xp0;   p1.C1 = xp1;
    p1.M = Bn * MAXL; p1.N = G3; p1.K = D_DIM;
    gemm_tc<MODE_GATHER, EPI_NONE>
        <<<dim3(G3 / 128, p1.M / 128, 2), 256>>>(p1);

    // --- 2) Recurrence: t=0 has h=0 (no GEMM); t=1..7 GEMM+gates ---
    GateP gp;
    gp.xp0 = xp0; gp.xp1 = xp1;
    gp.gh0 = gh0; gp.gh1 = gh1;
    gp.h0  = h0;  gp.h1  = h1;
    gp.bih0 = bih_f; gp.bih1 = bih_b;
    gp.bhh0 = bhh_f; gp.bhh1 = bhh_b;
    gp.wlen = wlen;

    const dim3 ggrid((Bn * (H_DIM / 4)) / 256, 1, 2);
    gp.t = 0;
    gru_gate<<<ggrid, 256>>>(gp);

    GemmP p2 = {};
    p2.A0 = h0; p2.A1 = h1;
    p2.B0 = Whh_f; p2.B1 = Whh_b;
    p2.C0 = gh0;   p2.C1 = gh1;
    p2.M = Bn; p2.N = G3; p2.K = H_DIM;
    for (int t = 1; t < MAXL; ++t) {
        gemm_tc<MODE_PLAIN, EPI_NONE>
            <<<dim3(G3 / 128, Bn / 128, 2), 256>>>(p2);
        gp.t = t;
        gru_gate<<<ggrid, 256>>>(gp);
    }

    // --- 3) MLP: relu([h_f,h_b] @ W1^T + b1) @ W2^T + b2 ---
    GemmP p3 = {};
    p3.A0 = h0; p3.A1 = h1;
    p3.B0 = W1; p3.B1 = W1;
    p3.C0 = hid; p3.C1 = hid;
    p3.bias = b1;
    p3.M = Bn; p3.N = H_DIM; p3.K = 2 * H_DIM;
    gemm_tc<MODE_CONCAT, EPI_BIAS_RELU>
        <<<dim3(H_DIM / 128, Bn / 128, 1), 256>>>(p3);

    GemmP p4 = {};
    p4.A0 = hid; p4.A1 = hid;
    p4.B0 = W2;  p4.B1 = W2;
    p4.C0 = out; p4.C1 = out;
    p4.bias = b2;
    p4.M = Bn; p4.N = H_DIM; p4.K = H_DIM;
    gemm_tc<MODE_PLAIN, EPI_BIAS>
        <<<dim3(H_DIM / 128, Bn / 128, 1), 256>>>(p4);
}

// round 4
// speedup vs baseline: 3.4164x; 1.5066x over previous
#include <cuda_runtime.h>
#include <math.h>
#include <cstdint>

// ---------------------------------------------------------------------------
// Problem constants: B=8192, T=15, D=H=512, MAXL=8, CENTER=7
// ---------------------------------------------------------------------------
#define B_MAX   8192
#define T_WIN   15
#define D_DIM   512
#define H_DIM   512
#define G3      1536
#define MAXL    8

#define PITCH   20                 // smem row pitch in floats (conflict-free)
#define STAGES  4                  // cp.async pipeline depth (K16 stages)
#define STAGE_FLOATS (128 * PITCH) // 2560 floats = 10240 B per matrix stage
#define SMEM_REQ (STAGES * STAGE_FLOATS * 4 * 2)   // 81920 B

// ---------------------------------------------------------------------------
// Scratch (__device__ globals)
// ---------------------------------------------------------------------------
__device__ float g_xp0[B_MAX * MAXL * G3];
__device__ float g_xp1[B_MAX * MAXL * G3];
__device__ float g_gh0[B_MAX * G3];
__device__ float g_gh1[B_MAX * G3];
__device__ float g_h0 [B_MAX * H_DIM];
__device__ float g_h1 [B_MAX * H_DIM];
__device__ float g_hid[B_MAX * H_DIM];
__device__ float g_winr[B_MAX * T_WIN * D_DIM];    // tf32-rounded window
// rounded weights, packed: Wih_f | Whh_f | Wih_b | Whh_b | W1 | W2
#define WR_WIHF 0
#define WR_WHHF (G3 * D_DIM)
#define WR_WIHB (2 * G3 * D_DIM)
#define WR_WHHB (3 * G3 * D_DIM)
#define WR_W1   (4 * G3 * D_DIM)
#define WR_W2   (4 * G3 * D_DIM + H_DIM * 2 * H_DIM)
__device__ float g_wr[4 * G3 * D_DIM + H_DIM * 2 * H_DIM + H_DIM * H_DIM];

// ---------------------------------------------------------------------------
// PTX helpers
// ---------------------------------------------------------------------------
__device__ __forceinline__ unsigned f2tf32(float f) {
    unsigned r;
    asm("cvt.rna.tf32.f32 %0, %1;" : "=r"(r) : "f"(f));
    return r;
}

__device__ __forceinline__ void ldsm4(unsigned* r, const float* p) {
    unsigned addr = (unsigned)__cvta_generic_to_shared(p);
    asm volatile("ldmatrix.sync.aligned.m8n8.x4.shared.b16 {%0,%1,%2,%3}, [%4];"
                 : "=r"(r[0]), "=r"(r[1]), "=r"(r[2]), "=r"(r[3]) : "r"(addr));
}

__device__ __forceinline__ void mma_tf32(float* c, const unsigned* a,
                                         unsigned b0, unsigned b1) {
    asm volatile(
        "mma.sync.aligned.m16n8k8.row.col.f32.tf32.tf32.f32 "
        "{%0,%1,%2,%3}, {%4,%5,%6,%7}, {%8,%9}, {%0,%1,%2,%3};"
        : "+f"(c[0]), "+f"(c[1]), "+f"(c[2]), "+f"(c[3])
        : "r"(a[0]), "r"(a[1]), "r"(a[2]), "r"(a[3]), "r"(b0), "r"(b1));
}

__device__ __forceinline__ void cpasync16(void* sp, const void* gp) {
    unsigned sa = (unsigned)__cvta_generic_to_shared(sp);
    asm volatile("cp.async.cg.shared.global [%0], [%1], 16;"
                 :: "r"(sa), "l"(gp) : "memory");
}
#define CP_COMMIT() asm volatile("cp.async.commit_group;" ::: "memory")
#define CP_WAIT(N)  asm volatile("cp.async.wait_group %0;" :: "n"(N) : "memory")

// ---------------------------------------------------------------------------
// Pre-round fp32 -> canonical tf32 bit patterns (done once per input matrix)
// ---------------------------------------------------------------------------
__global__ void preround(const float4* __restrict__ src,
                         float4* __restrict__ dst, int n4) {
    int i = blockIdx.x * blockDim.x + threadIdx.x;
    if (i >= n4) return;
    float4 v = src[i];
    v.x = __uint_as_float(f2tf32(v.x));
    v.y = __uint_as_float(f2tf32(v.y));
    v.z = __uint_as_float(f2tf32(v.z));
    v.w = __uint_as_float(f2tf32(v.w));
    dst[i] = v;
}

// ---------------------------------------------------------------------------
// Tensor-core NT GEMM:  C[M,N] = A[M,K] @ B[N,K]^T  (+bias, +relu, +tf32-round)
// Inputs are pre-rounded tf32 bit patterns -> no conversions in the kernel.
// 128x128 block, K16 stages, 4-deep cp.async pipeline, 256 thr, 2 CTAs/SM.
// ---------------------------------------------------------------------------
enum { MODE_GATHER = 0, MODE_PLAIN = 1, MODE_CONCAT = 2 };
enum { EPI_NONE = 0, EPI_BIAS = 1, EPI_BIAS_RELU = 2 };

struct GemmP {
    const float* A0;
    const float* A1;
    const float* B0;
    const float* B1;
    float*       C0;
    float*       C1;
    const float* win;
    const int*   wlen;
    const float* bias;
    int M, N, K;
};

template<int MODE, int EPI, int RND>
__global__ __launch_bounds__(256, 2)
void gemm_tc(GemmP p)
{
    extern __shared__ char dsm[];
    float* As = (float*)dsm;                                // [STAGES][128][20]
    float* Bs = (float*)(dsm + STAGES * STAGE_FLOATS * 4);

    const int dir = blockIdx.z;
    const float* __restrict__ Bmat = dir ? p.B1 : p.B0;
    float* __restrict__ C          = dir ? p.C1 : p.C0;
    const int K = p.K;
    const int N = p.N;

    const int tid  = threadIdx.x;
    const int bm   = blockIdx.y;
    const int bn   = blockIdx.x;
    const int warp = tid >> 5;
    const int lane = tid & 31;
    const int wm   = (warp >> 1) * 32;
    const int wn   = (warp & 1) * 64;

    // global-load mapping: rows lr, lr+64; k chunk lc (4 floats = 16B)
    const int lr = tid >> 2;
    const int lc = (tid & 3) * 4;

    const float* arow0 = nullptr;
    const float* arow1 = nullptr;
    int arix = bm * 128 + lr;

    if (MODE == MODE_GATHER) {
        #pragma unroll
        for (int q = 0; q < 2; ++q) {
            int r  = bm * 128 + lr + q * 64;
            int b  = r >> 3;
            int j  = r & 7;
            int wl = p.wlen[b];
            int idx;
            if (dir == 0) { int len = (wl - 1) / 2 + 1; idx = 8 - len + j; }
            else          { int len =  wl      / 2 + 1; idx = 6 + len - j; }
            idx = min(max(idx, 0), T_WIN - 1);
            const float* rp = p.win + ((size_t)b * T_WIN + idx) * D_DIM;
            if (q == 0) arow0 = rp; else arow1 = rp;
        }
    } else if (MODE == MODE_PLAIN) {
        const float* Abase = dir ? p.A1 : p.A0;
        arow0 = Abase + (size_t)(bm * 128 + lr) * K;
        arow1 = arow0 + (size_t)64 * K;
    }

    const float* brow0 = Bmat + (size_t)(bn * 128 + lr) * K;
    const float* brow1 = brow0 + (size_t)64 * K;

    float acc[2][8][4];
    #pragma unroll
    for (int i = 0; i < 2; ++i)
        #pragma unroll
        for (int t = 0; t < 8; ++t)
            #pragma unroll
            for (int v = 0; v < 4; ++v) acc[i][t][v] = 0.f;

    const int KT = K >> 4;

#define LOAD_STAGE(S, KT_IDX)                                                  \
    do {                                                                       \
        if ((KT_IDX) < KT) {                                                   \
            const int K0 = (KT_IDX) * 16;                                      \
            float* da0 = As + (S) * STAGE_FLOATS + lr * PITCH + lc;            \
            float* db0 = Bs + (S) * STAGE_FLOATS + lr * PITCH + lc;            \
            const float *pa0, *pa1;                                            \
            if (MODE == MODE_CONCAT) {                                         \
                const float* base = (K0 < 512) ? p.A0 : p.A1;                  \
                pa0 = base + (size_t)arix * 512 + (K0 & 511) + lc;             \
                pa1 = pa0 + (size_t)64 * 512;                                  \
            } else {                                                           \
                pa0 = arow0 + K0 + lc;                                         \
                pa1 = arow1 + K0 + lc;                                         \
            }                                                                  \
            cpasync16(da0,              pa0);                                  \
            cpasync16(da0 + 64 * PITCH, pa1);                                  \
            cpasync16(db0,              brow0 + K0 + lc);                      \
            cpasync16(db0 + 64 * PITCH, brow1 + K0 + lc);                      \
        }                                                                      \
        CP_COMMIT();                                                           \
    } while (0)

    // prologue: fill STAGES-1 stages
    #pragma unroll
    for (int s = 0; s < STAGES - 1; ++s) LOAD_STAGE(s, s);

    for (int kt = 0; kt < KT; ++kt) {
        CP_WAIT(STAGES - 2);
        __syncthreads();

        const int buf = kt & (STAGES - 1);
        const float* Ab = As + buf * STAGE_FLOATS;
        const float* Bb = Bs + buf * STAGE_FLOATS;

        #pragma unroll
        for (int ks = 0; ks < 2; ++ks) {
            const int k0 = ks * 8;
            unsigned a[2][4];
            #pragma unroll
            for (int i = 0; i < 2; ++i)
                ldsm4(a[i], Ab + (wm + i * 16 + (lane & 15)) * PITCH
                               + k0 + (lane >> 4) * 4);
            unsigned b[4][4];
            #pragma unroll
            for (int t4 = 0; t4 < 4; ++t4)
                ldsm4(b[t4], Bb + (wn + t4 * 16 + ((lane >> 4) << 3)
                                   + (lane & 7)) * PITCH
                                + k0 + ((lane >> 3) & 1) * 4);
            #pragma unroll
            for (int i = 0; i < 2; ++i)
                #pragma unroll
                for (int t4 = 0; t4 < 4; ++t4) {
                    mma_tf32(acc[i][2 * t4],     a[i], b[t4][0], b[t4][1]);
                    mma_tf32(acc[i][2 * t4 + 1], a[i], b[t4][2], b[t4][3]);
                }
        }

        LOAD_STAGE((kt + STAGES - 1) & (STAGES - 1), kt + STAGES - 1);
    }
#undef LOAD_STAGE

    // ---- epilogue: fragment (row = lane>>2 [+8], cols = 2*(lane&3)+{0,1})
    const int qr = lane >> 2;
    const int qc = (lane & 3) * 2;
    #pragma unroll
    for (int i = 0; i < 2; ++i) {
        const int r0 = bm * 128 + wm + i * 16 + qr;
        #pragma unroll
        for (int t = 0; t < 8; ++t) {
            const int cc = bn * 128 + wn + t * 8 + qc;
            float v0 = acc[i][t][0], v1 = acc[i][t][1];
            float v2 = acc[i][t][2], v3 = acc[i][t][3];
            if (EPI != EPI_NONE) {
                float b0 = p.bias[cc], b1 = p.bias[cc + 1];
                v0 += b0; v1 += b1; v2 += b0; v3 += b1;
                if (EPI == EPI_BIAS_RELU) {
                    v0 = fmaxf(v0, 0.f); v1 = fmaxf(v1, 0.f);
                    v2 = fmaxf(v2, 0.f); v3 = fmaxf(v3, 0.f);
                }
            }
            if (RND) {
                v0 = __uint_as_float(f2tf32(v0));
                v1 = __uint_as_float(f2tf32(v1));
                v2 = __uint_as_float(f2tf32(v2));
                v3 = __uint_as_float(f2tf32(v3));
            }
            *(float2*)(C + (size_t)r0       * N + cc) = make_float2(v0, v1);
            *(float2*)(C + (size_t)(r0 + 8) * N + cc) = make_float2(v2, v3);
        }
    }
}

// ---------------------------------------------------------------------------
// GRU gate update. Outputs h pre-rounded to tf32 (h feeds the next GEMM).
// ---------------------------------------------------------------------------
struct GateP {
    const float* xp0; const float* xp1;
    const float* gh0; const float* gh1;
    float*       h0;  float*       h1;
    const float* bih0; const float* bih1;
    const float* bhh0; const float* bhh1;
    const int*   wlen;
    int t;
};

__global__ void gru_gate(GateP p)
{
    const int dir = blockIdx.z;
    const int gi  = blockIdx.x * blockDim.x + threadIdx.x;
    const int b   = gi >> 7;
    const int j   = (gi & 127) * 4;

    const int wl  = p.wlen[b];
    const int len = dir ? (wl / 2 + 1) : ((wl - 1) / 2 + 1);
    const int t   = p.t;
    if (t >= len) return;

    const float* xp = (dir ? p.xp1 : p.xp0) + ((size_t)(b * MAXL + t)) * G3 + j;
    float4 xr = *(const float4*)(xp);
    float4 xz = *(const float4*)(xp + 512);
    float4 xn = *(const float4*)(xp + 1024);

    const float* bih = (dir ? p.bih1 : p.bih0) + j;
    const float* bhh = (dir ? p.bhh1 : p.bhh0) + j;
    float4 br = *(const float4*)(bih);
    float4 bz = *(const float4*)(bih + 512);
    float4 bq = *(const float4*)(bih + 1024);
    float4 cr = *(const float4*)(bhh);
    float4 cz = *(const float4*)(bhh + 512);
    float4 cq = *(const float4*)(bhh + 1024);

    float* hp = (dir ? p.h1 : p.h0) + (size_t)b * H_DIM + j;
    float4 hr, hz, hq, hv;
    if (t > 0) {
        const float* gh = (dir ? p.gh1 : p.gh0) + (size_t)b * G3 + j;
        hr = *(const float4*)(gh);
        hz = *(const float4*)(gh + 512);
        hq = *(const float4*)(gh + 1024);
        hv = *(const float4*)(hp);
    } else {
        hr = hz = hq = make_float4(0.f, 0.f, 0.f, 0.f);
        hv = make_float4(0.f, 0.f, 0.f, 0.f);
    }

    float4 res;
#define GATE(c)                                                                \
    {                                                                          \
        float r = 1.f / (1.f + expf(-(xr.c + br.c + hr.c + cr.c)));            \
        float z = 1.f / (1.f + expf(-(xz.c + bz.c + hz.c + cz.c)));            \
        float n = tanhf(xn.c + bq.c + r * (hq.c + cq.c));                      \
        float h = (1.f - z) * n + z * hv.c;                                    \
        res.c = __uint_as_float(f2tf32(h));                                    \
    }
    GATE(x) GATE(y) GATE(z) GATE(w)
#undef GATE
    *(float4*)hp = res;
}

// ---------------------------------------------------------------------------
// Launch sequence (graph-capturable)
// ---------------------------------------------------------------------------
extern "C" void kernel_launch(void* const* d_in, const int* in_sizes, int n_in,
                              void* d_out, int out_size)
{
    const float* win   = (const float*)d_in[0];
    const int*   wlen  = (const int*)  d_in[1];
    const float* Wih_f = (const float*)d_in[2];
    const float* Whh_f = (const float*)d_in[3];
    const float* bih_f = (const float*)d_in[4];
    const float* bhh_f = (const float*)d_in[5];
    const float* Wih_b = (const float*)d_in[6];
    const float* Whh_b = (const float*)d_in[7];
    const float* bih_b = (const float*)d_in[8];
    const float* bhh_b = (const float*)d_in[9];
    const float* W1    = (const float*)d_in[10];
    const float* b1    = (const float*)d_in[11];
    const float* W2    = (const float*)d_in[12];
    const float* b2    = (const float*)d_in[13];
    float* out = (float*)d_out;

    const int Bn = in_sizes[1];

    float *xp0, *xp1, *gh0, *gh1, *h0, *h1, *hid, *winr, *wr;
    cudaGetSymbolAddress((void**)&xp0,  g_xp0);
    cudaGetSymbolAddress((void**)&xp1,  g_xp1);
    cudaGetSymbolAddress((void**)&gh0,  g_gh0);
    cudaGetSymbolAddress((void**)&gh1,  g_gh1);
    cudaGetSymbolAddress((void**)&h0,   g_h0);
    cudaGetSymbolAddress((void**)&h1,   g_h1);
    cudaGetSymbolAddress((void**)&hid,  g_hid);
    cudaGetSymbolAddress((void**)&winr, g_winr);
    cudaGetSymbolAddress((void**)&wr,   g_wr);

    static bool attr_done = false;
    if (!attr_done) {
        cudaFuncSetAttribute(gemm_tc<MODE_GATHER, EPI_NONE, 0>,
                             cudaFuncAttributeMaxDynamicSharedMemorySize, SMEM_REQ);
        cudaFuncSetAttribute(gemm_tc<MODE_PLAIN, EPI_NONE, 0>,
                             cudaFuncAttributeMaxDynamicSharedMemorySize, SMEM_REQ);
        cudaFuncSetAttribute(gemm_tc<MODE_CONCAT, EPI_BIAS_RELU, 1>,
                             cudaFuncAttributeMaxDynamicSharedMemorySize, SMEM_REQ);
        cudaFuncSetAttribute(gemm_tc<MODE_PLAIN, EPI_BIAS, 0>,
                             cudaFuncAttributeMaxDynamicSharedMemorySize, SMEM_REQ);
        attr_done = true;
    }

    // --- 0) Pre-round GEMM inputs to canonical tf32 bit patterns ---
    {
        int n4 = Bn * T_WIN * D_DIM / 4;
        preround<<<(n4 + 255) / 256, 256>>>((const float4*)win,
                                            (float4*)winr, n4);
        int w4 = G3 * D_DIM / 4;
        preround<<<(w4 + 255) / 256, 256>>>((const float4*)Wih_f,
                                            (float4*)(wr + WR_WIHF), w4);
        preround<<<(w4 + 255) / 256, 256>>>((const float4*)Whh_f,
                                            (float4*)(wr + WR_WHHF), w4);
        preround<<<(w4 + 255) / 256, 256>>>((const float4*)Wih_b,
                                            (float4*)(wr + WR_WIHB), w4);
        preround<<<(w4 + 255) / 256, 256>>>((const float4*)Whh_b,
                                            (float4*)(wr + WR_WHHB), w4);
        int m4 = H_DIM * 2 * H_DIM / 4;
        preround<<<(m4 + 255) / 256, 256>>>((const float4*)W1,
                                            (float4*)(wr + WR_W1), m4);
        int o4 = H_DIM * H_DIM / 4;
        preround<<<(o4 + 255) / 256, 256>>>((const float4*)W2,
                                            (float4*)(wr + WR_W2), o4);
    }

    // --- 1) Input projections for all 8 steps, both directions (gathered) ---
    GemmP p1 = {};
    p1.win = winr; p1.wlen = wlen;
    p1.B0 = wr + WR_WIHF; p1.B1 = wr + WR_WIHB;
    p1.C0 = xp0;          p1.C1 = xp1;
    p1.M = Bn * MAXL; p1.N = G3; p1.K = D_DIM;
    gemm_tc<MODE_GATHER, EPI_NONE, 0>
        <<<dim3(G3 / 128, p1.M / 128, 2), 256, SMEM_REQ>>>(p1);

    // --- 2) Recurrence: t=0 has h=0 (no GEMM); t=1..7 GEMM+gates ---
    GateP gp;
    gp.xp0 = xp0; gp.xp1 = xp1;
    gp.gh0 = gh0; gp.gh1 = gh1;
    gp.h0  = h0;  gp.h1  = h1;
    gp.bih0 = bih_f; gp.bih1 = bih_b;
    gp.bhh0 = bhh_f; gp.bhh1 = bhh_b;
    gp.wlen = wlen;

    const dim3 ggrid((Bn * (H_DIM / 4)) / 256, 1, 2);
    gp.t = 0;
    gru_gate<<<ggrid, 256>>>(gp);

    GemmP p2 = {};
    p2.A0 = h0; p2.A1 = h1;
    p2.B0 = wr + WR_WHHF; p2.B1 = wr + WR_WHHB;
    p2.C0 = gh0;          p2.C1 = gh1;
    p2.M = Bn; p2.N = G3; p2.K = H_DIM;
    for (int t = 1; t < MAXL; ++t) {
        gemm_tc<MODE_PLAIN, EPI_NONE, 0>
            <<<dim3(G3 / 128, Bn / 128, 2), 256, SMEM_REQ>>>(p2);
        gp.t = t;
        gru_gate<<<ggrid, 256>>>(gp);
    }

    // --- 3) MLP: relu([h_f,h_b] @ W1^T + b1) @ W2^T + b2 ---
    GemmP p3 = {};
    p3.A0 = h0; p3.A1 = h1;
    p3.B0 = wr + WR_W1; p3.B1 = wr + WR_W1;
    p3.C0 = hid; p3.C1 = hid;
    p3.bias = b1;
    p3.M = Bn; p3.N = H_DIM; p3.K = 2 * H_DIM;
    gemm_tc<MODE_CONCAT, EPI_BIAS_RELU, 1>
        <<<dim3(H_DIM / 128, Bn / 128, 1), 256, SMEM_REQ>>>(p3);

    GemmP p4 = {};
    p4.A0 = hid; p4.A1 = hid;
    p4.B0 = wr + WR_W2; p4.B1 = wr + WR_W2;
    p4.C0 = out; p4.C1 = out;
    p4.bias = b2;
    p4.M = Bn; p4.N = H_DIM; p4.K = H_DIM;
    gemm_tc<MODE_PLAIN, EPI_BIAS, 0>
        <<<dim3(H_DIM / 128, Bn / 128, 1), 256, SMEM_REQ>>>(p4);
}

// round 5
// speedup vs baseline: 5.3683x; 1.5713x over previous
#include <cuda_runtime.h>
#include <math.h>
#include <cstdint>

// ---------------------------------------------------------------------------
// Problem constants: B=8192, T=15, D=H=512, MAXL=8, CENTER=7
// ---------------------------------------------------------------------------
#define B_MAX   8192
#define T_WIN   15
#define D_DIM   512
#define H_DIM   512
#define G3      1536
#define MAXL    8

#define PITCH   20
#define STAGES  4
#define STAGE_FLOATS (128 * PITCH)
#define SMEM_REQ (STAGES * STAGE_FLOATS * 4 * 2)   // 81920 B

// ---------------------------------------------------------------------------
// Scratch (__device__ globals)
// ---------------------------------------------------------------------------
__device__ float g_xp0[B_MAX * MAXL * G3];   // [t][sorted_i][1536]
__device__ float g_xp1[B_MAX * MAXL * G3];
__device__ float g_gh0[B_MAX * G3];
__device__ float g_gh1[B_MAX * G3];
__device__ float g_h0 [B_MAX * H_DIM];       // sorted order
__device__ float g_h1 [B_MAX * H_DIM];
__device__ float g_hid[B_MAX * H_DIM];
__device__ float g_winr[B_MAX * T_WIN * D_DIM];
#define WR_WIHF 0
#define WR_WHHF (G3 * D_DIM)
#define WR_WIHB (2 * G3 * D_DIM)
#define WR_WHHB (3 * G3 * D_DIM)
#define WR_W1   (4 * G3 * D_DIM)
#define WR_W2   (4 * G3 * D_DIM + H_DIM * 2 * H_DIM)
__device__ float g_wr[4 * G3 * D_DIM + H_DIM * 2 * H_DIM + H_DIM * H_DIM];

// ---- length-compaction state (deterministic counting sort by wl desc) ----
#define MAX_CHUNKS 64
__device__ int g_chunk_hist[MAX_CHUNKS][16];
__device__ int g_chunk_base[MAX_CHUNKS][16];
__device__ int g_lrank [B_MAX];
__device__ int g_perm  [B_MAX];   // sorted pos -> original batch idx
__device__ int g_lenf_s[B_MAX];   // sorted (descending) lens
__device__ int g_lenb_s[B_MAX];
__device__ int g_nt[2 * MAXL];    // [dir][t] = #rows with len > t

// ---------------------------------------------------------------------------
// PTX helpers
// ---------------------------------------------------------------------------
__device__ __forceinline__ unsigned f2tf32(float f) {
    unsigned r;
    asm("cvt.rna.tf32.f32 %0, %1;" : "=r"(r) : "f"(f));
    return r;
}

__device__ __forceinline__ void ldsm4(unsigned* r, const float* p) {
    unsigned addr = (unsigned)__cvta_generic_to_shared(p);
    asm volatile("ldmatrix.sync.aligned.m8n8.x4.shared.b16 {%0,%1,%2,%3}, [%4];"
                 : "=r"(r[0]), "=r"(r[1]), "=r"(r[2]), "=r"(r[3]) : "r"(addr));
}

__device__ __forceinline__ void mma_tf32(float* c, const unsigned* a,
                                         unsigned b0, unsigned b1) {
    asm volatile(
        "mma.sync.aligned.m16n8k8.row.col.f32.tf32.tf32.f32 "
        "{%0,%1,%2,%3}, {%4,%5,%6,%7}, {%8,%9}, {%0,%1,%2,%3};"
        : "+f"(c[0]), "+f"(c[1]), "+f"(c[2]), "+f"(c[3])
        : "r"(a[0]), "r"(a[1]), "r"(a[2]), "r"(a[3]), "r"(b0), "r"(b1));
}

__device__ __forceinline__ void cpasync16(void* sp, const void* gp) {
    unsigned sa = (unsigned)__cvta_generic_to_shared(sp);
    asm volatile("cp.async.cg.shared.global [%0], [%1], 16;"
                 :: "r"(sa), "l"(gp) : "memory");
}
#define CP_COMMIT() asm volatile("cp.async.commit_group;" ::: "memory")
#define CP_WAIT(N)  asm volatile("cp.async.wait_group %0;" :: "n"(N) : "memory")

// ---------------------------------------------------------------------------
// Pre-round fp32 -> canonical tf32 bit patterns
// ---------------------------------------------------------------------------
__global__ void preround(const float4* __restrict__ src,
                         float4* __restrict__ dst, int n4) {
    int i = blockIdx.x * blockDim.x + threadIdx.x;
    if (i >= n4) return;
    float4 v = src[i];
    v.x = __uint_as_float(f2tf32(v.x));
    v.y = __uint_as_float(f2tf32(v.y));
    v.z = __uint_as_float(f2tf32(v.z));
    v.w = __uint_as_float(f2tf32(v.w));
    dst[i] = v;
}

// ---------------------------------------------------------------------------
// Deterministic counting sort by window_len descending (3 tiny kernels)
// ---------------------------------------------------------------------------
__global__ void sort1(const int* __restrict__ wlen) {
    __shared__ int s_wl[256];
    __shared__ int s_rank[256];
    __shared__ int s_h[16];
    const int c = blockIdx.x, tid = threadIdx.x;
    s_wl[tid] = wlen[c * 256 + tid];
    if (tid < 16) s_h[tid] = 0;
    __syncthreads();
    if (tid == 0) {
        #pragma unroll 4
        for (int k = 0; k < 256; ++k) { int w = s_wl[k]; s_rank[k] = s_h[w]++; }
    }
    __syncthreads();
    g_lrank[c * 256 + tid] = s_rank[tid];
    if (tid < 16) g_chunk_hist[c][tid] = s_h[tid];
}

__global__ void sort2(int nchunks) {
    if (threadIdx.x != 0) return;
    int total[16];
    for (int w = 0; w < 16; ++w) {
        int s = 0;
        for (int c = 0; c < nchunks; ++c) s += g_chunk_hist[c][w];
        total[w] = s;
    }
    // bucket offsets, wl descending (wl=15 first)
    int off = 0;
    for (int w = 15; w >= 1; --w) {
        int run = off;
        for (int c = 0; c < nchunks; ++c) {
            g_chunk_base[c][w] = run;
            run += g_chunk_hist[c][w];
        }
        off += total[w];
    }
    // active counts: n_t = #{len > t}
    for (int t = 0; t < MAXL; ++t) {
        int nf = 0, nb = 0;
        for (int w = 1; w <= 15; ++w) {
            if ((w - 1) / 2 + 1 > t) nf += total[w];
            if (w / 2 + 1 > t)       nb += total[w];
        }
        g_nt[t]        = nf;
        g_nt[MAXL + t] = nb;
    }
}

__global__ void sort3(const int* __restrict__ wlen) {
    const int c = blockIdx.x;
    const int i = c * 256 + threadIdx.x;
    const int w = wlen[i];
    const int pos = g_chunk_base[c][w] + g_lrank[i];
    g_perm[pos]   = i;
    g_lenf_s[pos] = (w - 1) / 2 + 1;
    g_lenb_s[pos] = w / 2 + 1;
}

// ---------------------------------------------------------------------------
// Tensor-core NT GEMM with length-compaction early exit.
// ---------------------------------------------------------------------------
enum { MODE_GATHER = 0, MODE_PLAIN = 1, MODE_CONCAT = 2 };
enum { EPI_NONE = 0, EPI_BIAS = 1, EPI_BIAS_RELU = 2 };

struct GemmP {
    const float* A0;
    const float* A1;
    const float* B0;
    const float* B1;
    float*       C0;
    float*       C1;
    const float* win;
    const float* bias;
    const int*   perm;     // sorted pos -> batch (GATHER row source)
    const int*   lenf_s;
    const int*   lenb_s;
    const int*   nt;       // g_nt
    const int*   operm;    // output row scatter (final GEMM)
    int M, N, K, step, Bn;
};

template<int MODE, int EPI, int RND>
__global__ __launch_bounds__(256, 2)
void gemm_tc(GemmP p)
{
    const int dir = blockIdx.z;
    const int bm  = blockIdx.y;
    const int bn  = blockIdx.x;

    // ---- length-compaction early exit (n_t read from device memory) ----
    if (MODE == MODE_GATHER) {
        const int t  = (bm * 128) / p.Bn;
        const int i0 = (bm * 128) % p.Bn;
        if (i0 >= p.nt[dir * MAXL + t]) return;
    } else if (p.nt) {
        if (bm * 128 >= p.nt[dir * MAXL + p.step]) return;
    }

    extern __shared__ char dsm[];
    float* As = (float*)dsm;
    float* Bs = (float*)(dsm + STAGES * STAGE_FLOATS * 4);

    const float* __restrict__ Bmat = dir ? p.B1 : p.B0;
    float* __restrict__ C          = dir ? p.C1 : p.C0;
    const int K = p.K;
    const int N = p.N;

    const int tid  = threadIdx.x;
    const int warp = tid >> 5;
    const int lane = tid & 31;
    const int wm   = (warp >> 1) * 32;
    const int wn   = (warp & 1) * 64;

    const int lr = tid >> 2;
    const int lc = (tid & 3) * 4;

    const float* arow0 = nullptr;
    const float* arow1 = nullptr;
    int arix = bm * 128 + lr;

    if (MODE == MODE_GATHER) {
        #pragma unroll
        for (int q = 0; q < 2; ++q) {
            const int gr = bm * 128 + lr + q * 64;
            const int t  = gr / p.Bn;
            const int i  = gr % p.Bn;
            const int b  = p.perm[i];
            const int len = dir ? p.lenb_s[i] : p.lenf_s[i];
            int idx = dir ? (6 + len - t) : (8 - len + t);
            idx = min(max(idx, 0), T_WIN - 1);
            const float* rp = p.win + ((size_t)b * T_WIN + idx) * D_DIM;
            if (q == 0) arow0 = rp; else arow1 = rp;
        }
    } else if (MODE == MODE_PLAIN) {
        const float* Abase = dir ? p.A1 : p.A0;
        arow0 = Abase + (size_t)(bm * 128 + lr) * K;
        arow1 = arow0 + (size_t)64 * K;
    }

    const float* brow0 = Bmat + (size_t)(bn * 128 + lr) * K;
    const float* brow1 = brow0 + (size_t)64 * K;

    float acc[2][8][4];
    #pragma unroll
    for (int i = 0; i < 2; ++i)
        #pragma unroll
        for (int t = 0; t < 8; ++t)
            #pragma unroll
            for (int v = 0; v < 4; ++v) acc[i][t][v] = 0.f;

    const int KT = K >> 4;

#define LOAD_STAGE(S, KT_IDX)                                                  \
    do {                                                                       \
        if ((KT_IDX) < KT) {                                                   \
            const int K0 = (KT_IDX) * 16;                                      \
            float* da0 = As + (S) * STAGE_FLOATS + lr * PITCH + lc;            \
            float* db0 = Bs + (S) * STAGE_FLOATS + lr * PITCH + lc;            \
            const float *pa0, *pa1;                                            \
            if (MODE == MODE_CONCAT) {                                         \
                const float* base = (K0 < 512) ? p.A0 : p.A1;                  \
                pa0 = base + (size_t)arix * 512 + (K0 & 511) + lc;             \
                pa1 = pa0 + (size_t)64 * 512;                                  \
            } else {                                                           \
                pa0 = arow0 + K0 + lc;                                         \
                pa1 = arow1 + K0 + lc;                                         \
            }                                                                  \
            cpasync16(da0,              pa0);                                  \
            cpasync16(da0 + 64 * PITCH, pa1);                                  \
            cpasync16(db0,              brow0 + K0 + lc);                      \
            cpasync16(db0 + 64 * PITCH, brow1 + K0 + lc);                      \
        }                                                                      \
        CP_COMMIT();                                                           \
    } while (0)

    #pragma unroll
    for (int s = 0; s < STAGES - 1; ++s) LOAD_STAGE(s, s);

    for (int kt = 0; kt < KT; ++kt) {
        CP_WAIT(STAGES - 2);
        __syncthreads();

        const int buf = kt & (STAGES - 1);
        const float* Ab = As + buf * STAGE_FLOATS;
        const float* Bb = Bs + buf * STAGE_FLOATS;

        #pragma unroll
        for (int ks = 0; ks < 2; ++ks) {
            const int k0 = ks * 8;
            unsigned a[2][4];
            #pragma unroll
            for (int i = 0; i < 2; ++i)
                ldsm4(a[i], Ab + (wm + i * 16 + (lane & 15)) * PITCH
                               + k0 + (lane >> 4) * 4);
            unsigned b[4][4];
            #pragma unroll
            for (int t4 = 0; t4 < 4; ++t4)
                ldsm4(b[t4], Bb + (wn + t4 * 16 + ((lane >> 4) << 3)
                                   + (lane & 7)) * PITCH
                                + k0 + ((lane >> 3) & 1) * 4);
            #pragma unroll
            for (int i = 0; i < 2; ++i)
                #pragma unroll
                for (int t4 = 0; t4 < 4; ++t4) {
                    mma_tf32(acc[i][2 * t4],     a[i], b[t4][0], b[t4][1]);
                    mma_tf32(acc[i][2 * t4 + 1], a[i], b[t4][2], b[t4][3]);
                }
        }

        LOAD_STAGE((kt + STAGES - 1) & (STAGES - 1), kt + STAGES - 1);
    }
#undef LOAD_STAGE

    // ---- epilogue (optional output-row scatter via operm) ----
    const int qr = lane >> 2;
    const int qc = (lane & 3) * 2;
    #pragma unroll
    for (int i = 0; i < 2; ++i) {
        const int rA = bm * 128 + wm + i * 16 + qr;
        const int gA = p.operm ? p.operm[rA]     : rA;
        const int gB = p.operm ? p.operm[rA + 8] : rA + 8;
        #pragma unroll
        for (int t = 0; t < 8; ++t) {
            const int cc = bn * 128 + wn + t * 8 + qc;
            float v0 = acc[i][t][0], v1 = acc[i][t][1];
            float v2 = acc[i][t][2], v3 = acc[i][t][3];
            if (EPI != EPI_NONE) {
                float b0 = p.bias[cc], b1 = p.bias[cc + 1];
                v0 += b0; v1 += b1; v2 += b0; v3 += b1;
                if (EPI == EPI_BIAS_RELU) {
                    v0 = fmaxf(v0, 0.f); v1 = fmaxf(v1, 0.f);
                    v2 = fmaxf(v2, 0.f); v3 = fmaxf(v3, 0.f);
                }
            }
            if (RND) {
                v0 = __uint_as_float(f2tf32(v0));
                v1 = __uint_as_float(f2tf32(v1));
                v2 = __uint_as_float(f2tf32(v2));
                v3 = __uint_as_float(f2tf32(v3));
            }
            *(float2*)(C + (size_t)gA * N + cc) = make_float2(v0, v1);
            *(float2*)(C + (size_t)gB * N + cc) = make_float2(v2, v3);
        }
    }
}

// ---------------------------------------------------------------------------
// GRU gate update on sorted rows. Prefix property: i < n_t <=> row active.
// ---------------------------------------------------------------------------
struct GateP {
    const float* xp0; const float* xp1;
    const float* gh0; const float* gh1;
    float*       h0;  float*       h1;
    const float* bih0; const float* bih1;
    const float* bhh0; const float* bhh1;
    const int*   nt;
    int t, Bn;
};

__global__ void gru_gate(GateP p)
{
    const int dir = blockIdx.z;
    const int gi  = blockIdx.x * blockDim.x + threadIdx.x;
    const int i   = gi >> 7;           // sorted row
    const int j   = (gi & 127) * 4;
    const int t   = p.t;

    if (i >= p.nt[dir * MAXL + t]) return;   // sorted prefix = active set

    const float* xp = (dir ? p.xp1 : p.xp0)
                    + ((size_t)t * p.Bn + i) * G3 + j;
    float4 xr = *(const float4*)(xp);
    float4 xz = *(const float4*)(xp + 512);
    float4 xn = *(const float4*)(xp + 1024);

    const float* bih = (dir ? p.bih1 : p.bih0) + j;
    const float* bhh = (dir ? p.bhh1 : p.bhh0) + j;
    float4 br = *(const float4*)(bih);
    float4 bz = *(const float4*)(bih + 512);
    float4 bq = *(const float4*)(bih + 1024);
    float4 cr = *(const float4*)(bhh);
    float4 cz = *(const float4*)(bhh + 512);
    float4 cq = *(const float4*)(bhh + 1024);

    float* hp = (dir ? p.h1 : p.h0) + (size_t)i * H_DIM + j;
    float4 hr, hz, hq, hv;
    if (t > 0) {
        const float* gh = (dir ? p.gh1 : p.gh0) + (size_t)i * G3 + j;
        hr = *(const float4*)(gh);
        hz = *(const float4*)(gh + 512);
        hq = *(const float4*)(gh + 1024);
        hv = *(const float4*)(hp);
    } else {
        hr = hz = hq = make_float4(0.f, 0.f, 0.f, 0.f);
        hv = make_float4(0.f, 0.f, 0.f, 0.f);
    }

    float4 res;
#define GATE(c)                                                                \
    {                                                                          \
        float r = 1.f / (1.f + expf(-(xr.c + br.c + hr.c + cr.c)));            \
        float z = 1.f / (1.f + expf(-(xz.c + bz.c + hz.c + cz.c)));            \
        float n = tanhf(xn.c + bq.c + r * (hq.c + cq.c));                      \
        float h = (1.f - z) * n + z * hv.c;                                    \
        res.c = __uint_as_float(f2tf32(h));                                    \
    }
    GATE(x) GATE(y) GATE(z) GATE(w)
#undef GATE
    *(float4*)hp = res;
}

// ---------------------------------------------------------------------------
// Launch sequence (graph-capturable)
// ---------------------------------------------------------------------------
extern "C" void kernel_launch(void* const* d_in, const int* in_sizes, int n_in,
                              void* d_out, int out_size)
{
    const float* win   = (const float*)d_in[0];
    const int*   wlen  = (const int*)  d_in[1];
    const float* Wih_f = (const float*)d_in[2];
    const float* Whh_f = (const float*)d_in[3];
    const float* bih_f = (const float*)d_in[4];
    const float* bhh_f = (const float*)d_in[5];
    const float* Wih_b = (const float*)d_in[6];
    const float* Whh_b = (const float*)d_in[7];
    const float* bih_b = (const float*)d_in[8];
    const float* bhh_b = (const float*)d_in[9];
    const float* W1    = (const float*)d_in[10];
    const float* b1    = (const float*)d_in[11];
    const float* W2    = (const float*)d_in[12];
    const float* b2    = (const float*)d_in[13];
    float* out = (float*)d_out;

    const int Bn = in_sizes[1];

    float *xp0, *xp1, *gh0, *gh1, *h0, *h1, *hid, *winr, *wr;
    int *perm, *lenf_s, *lenb_s, *nt;
    cudaGetSymbolAddress((void**)&xp0,    g_xp0);
    cudaGetSymbolAddress((void**)&xp1,    g_xp1);
    cudaGetSymbolAddress((void**)&gh0,    g_gh0);
    cudaGetSymbolAddress((void**)&gh1,    g_gh1);
    cudaGetSymbolAddress((void**)&h0,     g_h0);
    cudaGetSymbolAddress((void**)&h1,     g_h1);
    cudaGetSymbolAddress((void**)&hid,    g_hid);
    cudaGetSymbolAddress((void**)&winr,   g_winr);
    cudaGetSymbolAddress((void**)&wr,     g_wr);
    cudaGetSymbolAddress((void**)&perm,   g_perm);
    cudaGetSymbolAddress((void**)&lenf_s, g_lenf_s);
    cudaGetSymbolAddress((void**)&lenb_s, g_lenb_s);
    cudaGetSymbolAddress((void**)&nt,     g_nt);

    static bool attr_done = false;
    if (!attr_done) {
        cudaFuncSetAttribute(gemm_tc<MODE_GATHER, EPI_NONE, 0>,
                             cudaFuncAttributeMaxDynamicSharedMemorySize, SMEM_REQ);
        cudaFuncSetAttribute(gemm_tc<MODE_PLAIN, EPI_NONE, 0>,
                             cudaFuncAttributeMaxDynamicSharedMemorySize, SMEM_REQ);
        cudaFuncSetAttribute(gemm_tc<MODE_CONCAT, EPI_BIAS_RELU, 1>,
                             cudaFuncAttributeMaxDynamicSharedMemorySize, SMEM_REQ);
        cudaFuncSetAttribute(gemm_tc<MODE_PLAIN, EPI_BIAS, 0>,
                             cudaFuncAttributeMaxDynamicSharedMemorySize, SMEM_REQ);
        attr_done = true;
    }

    // --- 0a) Pre-round GEMM inputs to canonical tf32 ---
    {
        int n4 = Bn * T_WIN * D_DIM / 4;
        preround<<<(n4 + 255) / 256, 256>>>((const float4*)win,
                                            (float4*)winr, n4);
        int w4 = G3 * D_DIM / 4;
        preround<<<(w4 + 255) / 256, 256>>>((const float4*)Wih_f,
                                            (float4*)(wr + WR_WIHF), w4);
        preround<<<(w4 + 255) / 256, 256>>>((const float4*)Whh_f,
                                            (float4*)(wr + WR_WHHF), w4);
        preround<<<(w4 + 255) / 256, 256>>>((const float4*)Wih_b,
                                            (float4*)(wr + WR_WIHB), w4);
        preround<<<(w4 + 255) / 256, 256>>>((const float4*)Whh_b,
                                            (float4*)(wr + WR_WHHB), w4);
        int m4 = H_DIM * 2 * H_DIM / 4;
        preround<<<(m4 + 255) / 256, 256>>>((const float4*)W1,
                                            (float4*)(wr + WR_W1), m4);
        int o4 = H_DIM * H_DIM / 4;
        preround<<<(o4 + 255) / 256, 256>>>((const float4*)W2,
                                            (float4*)(wr + WR_W2), o4);
    }

    // --- 0b) Deterministic counting sort by wl descending ---
    const int nchunks = Bn / 256;
    sort1<<<nchunks, 256>>>(wlen);
    sort2<<<1, 32>>>(nchunks);
    sort3<<<nchunks, 256>>>(wlen);

    // --- 1) Input projections, t-major sorted layout, compaction exit ---
    GemmP p1 = {};
    p1.win = winr;
    p1.B0 = wr + WR_WIHF; p1.B1 = wr + WR_WIHB;
    p1.C0 = xp0;          p1.C1 = xp1;
    p1.perm = perm; p1.lenf_s = lenf_s; p1.lenb_s = lenb_s; p1.nt = nt;
    p1.M = Bn * MAXL; p1.N = G3; p1.K = D_DIM; p1.Bn = Bn;
    gemm_tc<MODE_GATHER, EPI_NONE, 0>
        <<<dim3(G3 / 128, p1.M / 128, 2), 256, SMEM_REQ>>>(p1);

    // --- 2) Recurrence over sorted prefix ---
    GateP gp;
    gp.xp0 = xp0; gp.xp1 = xp1;
    gp.gh0 = gh0; gp.gh1 = gh1;
    gp.h0  = h0;  gp.h1  = h1;
    gp.bih0 = bih_f; gp.bih1 = bih_b;
    gp.bhh0 = bhh_f; gp.bhh1 = bhh_b;
    gp.nt = nt; gp.Bn = Bn;

    const dim3 ggrid((Bn * (H_DIM / 4)) / 256, 1, 2);
    gp.t = 0;
    gru_gate<<<ggrid, 256>>>(gp);

    GemmP p2 = {};
    p2.A0 = h0; p2.A1 = h1;
    p2.B0 = wr + WR_WHHF; p2.B1 = wr + WR_WHHB;
    p2.C0 = gh0;          p2.C1 = gh1;
    p2.nt = nt;
    p2.M = Bn; p2.N = G3; p2.K = H_DIM; p2.Bn = Bn;
    for (int t = 1; t < MAXL; ++t) {
        p2.step = t;
        gemm_tc<MODE_PLAIN, EPI_NONE, 0>
            <<<dim3(G3 / 128, Bn / 128, 2), 256, SMEM_REQ>>>(p2);
        gp.t = t;
        gru_gate<<<ggrid, 256>>>(gp);
    }

    // --- 3) MLP on sorted rows; final GEMM scatters to original order ---
    GemmP p3 = {};
    p3.A0 = h0; p3.A1 = h1;
    p3.B0 = wr + WR_W1; p3.B1 = wr + WR_W1;
    p3.C0 = hid; p3.C1 = hid;
    p3.bias = b1;
    p3.M = Bn; p3.N = H_DIM; p3.K = 2 * H_DIM; p3.Bn = Bn;
    gemm_tc<MODE_CONCAT, EPI_BIAS_RELU, 1>
        <<<dim3(H_DIM / 128, Bn / 128, 1), 256, SMEM_REQ>>>(p3);

    GemmP p4 = {};
    p4.A0 = hid; p4.A1 = hid;
    p4.B0 = wr + WR_W2; p4.B1 = wr + WR_W2;
    p4.C0 = out; p4.C1 = out;
    p4.bias = b2;
    p4.operm = perm;
    p4.M = Bn; p4.N = H_DIM; p4.K = H_DIM; p4.Bn = Bn;
    gemm_tc<MODE_PLAIN, EPI_BIAS, 0>
        <<<dim3(H_DIM / 128, Bn / 128, 1), 256, SMEM_REQ>>>(p4);
}